// round 9
// baseline (speedup 1.0000x reference)
#include <cuda_runtime.h>
#include <cstdint>

#define BB 4
#define HH 8
#define SS 2048
#define DD 512
#define DH 64
#define TOPK 10

// Scratch: Q,K transposed [bh][d][s] (d-major for attn GEMM staging);
// V row-major [bh][s][d] (context reads rows).
__device__ float g_Qt[BB*HH*DH*SS];
__device__ float g_Kt[BB*HH*DH*SS];
__device__ float g_V [BB*HH*SS*DH];

__device__ __forceinline__ float neg_inf() { return __int_as_float(0xff800000); }

__device__ __forceinline__ void cpa16(void* s, const void* g) {
    uint32_t sa = (uint32_t)__cvta_generic_to_shared(s);
    asm volatile("cp.async.cg.shared.global [%0], [%1], 16;" :: "r"(sa), "l"(g));
}
__device__ __forceinline__ void cpa_commit() {
    asm volatile("cp.async.commit_group;");
}
__device__ __forceinline__ void cpa_wait0() {
    asm volatile("cp.async.wait_group 0;");
}

// ---------------------------------------------------------------------------
// Kernel 1: Y = x @ W^T + b; Q,K scattered transposed, V row-major.
// Serial ascending-k FMA chain per output (bit-exact, matches reference).
// AT the 3-reg FFMA roofline — do not touch.
// ---------------------------------------------------------------------------
__global__ __launch_bounds__(256) void qkv_kernel(
    const float* __restrict__ x,
    const float* __restrict__ Wq, const float* __restrict__ bq,
    const float* __restrict__ Wk, const float* __restrict__ bk,
    const float* __restrict__ Wv, const float* __restrict__ bv)
{
    const int which = blockIdx.z;
    const float* __restrict__ W    = (which == 0) ? Wq : (which == 1) ? Wk : Wv;
    const float* __restrict__ bias = (which == 0) ? bq : (which == 1) ? bk : bv;

    __shared__ float As[16][68];   // [k][m], padded
    __shared__ float Bs[16][68];   // [k][n], padded

    const int tid = threadIdx.x;
    const int tx  = tid & 15;       // 0..15 -> n
    const int ty  = tid >> 4;       // 0..15 -> m
    const int m0  = blockIdx.y * 64;
    const int n0  = blockIdx.x * 64;   // one head per n-tile (DH==64)

    const int lrow = tid >> 2;      // 0..63
    const int lk4  = tid & 3;       // 0..3

    float c[4][4];
    #pragma unroll
    for (int i = 0; i < 4; ++i)
        #pragma unroll
        for (int j = 0; j < 4; ++j) c[i][j] = 0.f;

    for (int kt = 0; kt < DD / 16; ++kt) {
        float4 av = *(const float4*)&x[(size_t)(m0 + lrow) * DD + kt * 16 + lk4 * 4];
        float4 bv4 = *(const float4*)&W[(size_t)(n0 + lrow) * DD + kt * 16 + lk4 * 4];
        __syncthreads();
        As[lk4 * 4 + 0][lrow] = av.x;
        As[lk4 * 4 + 1][lrow] = av.y;
        As[lk4 * 4 + 2][lrow] = av.z;
        As[lk4 * 4 + 3][lrow] = av.w;
        Bs[lk4 * 4 + 0][lrow] = bv4.x;
        Bs[lk4 * 4 + 1][lrow] = bv4.y;
        Bs[lk4 * 4 + 2][lrow] = bv4.z;
        Bs[lk4 * 4 + 3][lrow] = bv4.w;
        __syncthreads();
        // k ascending; each c[i][j] is one serial FMA chain over all 512 k.
        #pragma unroll
        for (int k = 0; k < 16; ++k) {
            float4 a  = *(const float4*)&As[k][ty * 4];
            float4 b4 = *(const float4*)&Bs[k][tx * 4];
            c[0][0] = fmaf(a.x, b4.x, c[0][0]); c[0][1] = fmaf(a.x, b4.y, c[0][1]);
            c[0][2] = fmaf(a.x, b4.z, c[0][2]); c[0][3] = fmaf(a.x, b4.w, c[0][3]);
            c[1][0] = fmaf(a.y, b4.x, c[1][0]); c[1][1] = fmaf(a.y, b4.y, c[1][1]);
            c[1][2] = fmaf(a.y, b4.z, c[1][2]); c[1][3] = fmaf(a.y, b4.w, c[1][3]);
            c[2][0] = fmaf(a.z, b4.x, c[2][0]); c[2][1] = fmaf(a.z, b4.y, c[2][1]);
            c[2][2] = fmaf(a.z, b4.z, c[2][2]); c[2][3] = fmaf(a.z, b4.w, c[2][3]);
            c[3][0] = fmaf(a.w, b4.x, c[3][0]); c[3][1] = fmaf(a.w, b4.y, c[3][1]);
            c[3][2] = fmaf(a.w, b4.z, c[3][2]); c[3][3] = fmaf(a.w, b4.w, c[3][3]);
        }
    }

    float4 biasv = *(const float4*)&bias[n0 + tx * 4];
    const int head = blockIdx.x;
    #pragma unroll
    for (int i = 0; i < 4; ++i) {
        int m  = m0 + ty * 4 + i;
        int b_ = m >> 11;        // m / 2048
        int s_ = m & 2047;
        float o0 = c[i][0] + biasv.x;
        float o1 = c[i][1] + biasv.y;
        float o2 = c[i][2] + biasv.z;
        float o3 = c[i][3] + biasv.w;
        if (which == 2) {
            float4 o; o.x = o0; o.y = o1; o.z = o2; o.w = o3;
            *(float4*)&g_V[(size_t)(((b_ * HH + head) * SS) + s_) * DH + tx * 4] = o;
        } else {
            float* dst = (which == 0) ? g_Qt : g_Kt;
            size_t base = ((size_t)(b_ * HH + head) * DH + tx * 4) * SS + s_;
            dst[base + 0 * SS] = o0;
            dst[base + 1 * SS] = o1;
            dst[base + 2 * SS] = o2;
            dst[base + 3 * SS] = o3;
        }
    }
}

// ---------------------------------------------------------------------------
// Kernel 2: per (b,h, 32-q-row tile). 128 threads; each computes a 4q x 8k
// sub-tile of a 32q x 128k score tile (k split: cols tx*4 and 64+tx*4 so
// both K loads are contiguous/conflict-free). Per d-step: 3 LDS.128 -> 32 FMA.
// d-loop strictly serial ascending per accumulator (bit-exact chain).
// 16 k-tiles (half the barriers of the 64-wide version); cp.async prefetch
// overlaps the scan. Sc stride 132 (== 4 mod 32: dump & scan both optimal
// 4 wavefronts). Scan keeps per-thread top-10; merge 4 lists/row; softmax;
// scatter attn (rest pre-zeroed by memset); context from V rows.
// ---------------------------------------------------------------------------
__global__ __launch_bounds__(128, 3) void attn_kernel(
    float* __restrict__ out_ctx, float* __restrict__ out_attn)
{
    extern __shared__ float sm[];
    float* As = sm;                  // 64 x 36   [d][q]   (2304 floats)
    float* Bs = sm + 2304;           // 64 x 128  [d][k]   (8192 floats)
    float* Sc = sm + 10496;          // 32 x 132  [q][k]   (4224 floats)
    // Post-loop overlays (dead regions after the k-loop):
    float* cv  = Bs;                 // 128*10 floats
    int*   ci  = (int*)(Bs + 1280);  // 128*10 ints
    float* pb  = As;                 // 32*10 floats
    int*   tix = (int*)(As + 320);   // 32*10 ints

    const int qt  = blockIdx.x;      // 0..63 (32 q-rows each)
    const int bh  = blockIdx.y;      // 0..31
    const int tid = threadIdx.x;     // 0..127
    const int ty  = tid >> 4;        // 0..7  -> q rows ty*4..+3
    const int tx  = tid & 15;        // 0..15 -> k cols tx*4..+3 and 64+tx*4..+3
    const int srow = tid >> 2;       // 0..31 scan row
    const int scg  = tid & 3;        // 0..3  scan col group

    const float* __restrict__ Qt = g_Qt + (size_t)bh * DH * SS;
    const float* __restrict__ Kt = g_Kt + (size_t)bh * DH * SS;
    const float* __restrict__ Vb = g_V  + (size_t)bh * SS * DH;

    // Stage As = Q^T tile (64d x 32q), scaled by 1/8 (exact pow2).
    #pragma unroll
    for (int p = 0; p < 4; ++p) {
        int idx = p * 128 + tid;     // 0..511 float4s
        int d   = idx >> 3;
        int qf4 = idx & 7;
        float4 v = *(const float4*)&Qt[(size_t)d * SS + qt * 32 + qf4 * 4];
        v.x *= 0.125f; v.y *= 0.125f; v.z *= 0.125f; v.w *= 0.125f;
        *(float4*)&As[d * 36 + qf4 * 4] = v;
    }

    // Preload K tile 0 via cp.async (16 float4 per thread).
    #pragma unroll
    for (int p = 0; p < 16; ++p) {
        int idx = p * 128 + tid;     // 0..2047 float4s
        int d   = idx >> 5;
        int kf4 = idx & 31;
        cpa16(&Bs[d * 128 + kf4 * 4], &Kt[(size_t)d * SS + kf4 * 4]);
    }
    cpa_commit();
    cpa_wait0();
    __syncthreads();                  // As + Bs(tile 0) ready

    float tv[TOPK];
    int   ti[TOPK];
    #pragma unroll
    for (int t = 0; t < TOPK; ++t) { tv[t] = neg_inf(); ti[t] = 0x7FFFFFFF; }

    for (int kt = 0; kt < SS / 128; ++kt) {
        // GEMM: 4q x 8k accumulators, d ascending serial per accumulator.
        float a[4][8];
        #pragma unroll
        for (int i = 0; i < 4; ++i)
            #pragma unroll
            for (int j = 0; j < 8; ++j) a[i][j] = 0.f;
        #pragma unroll 8
        for (int d = 0; d < 64; ++d) {
            float4 q  = *(const float4*)&As[d * 36 + ty * 4];
            float4 k0 = *(const float4*)&Bs[d * 128 + tx * 4];
            float4 k1 = *(const float4*)&Bs[d * 128 + 64 + tx * 4];
            float qq[4] = {q.x, q.y, q.z, q.w};
            float kk[8] = {k0.x, k0.y, k0.z, k0.w, k1.x, k1.y, k1.z, k1.w};
            #pragma unroll
            for (int i = 0; i < 4; ++i)
                #pragma unroll
                for (int j = 0; j < 8; ++j)
                    a[i][j] = fmaf(qq[i], kk[j], a[i][j]);
        }
        // Dump scores: low half at col tx*4, high half at col 64+tx*4.
        #pragma unroll
        for (int i = 0; i < 4; ++i) {
            *(float4*)&Sc[(ty*4+i) * 132 + tx*4]      = make_float4(a[i][0], a[i][1], a[i][2], a[i][3]);
            *(float4*)&Sc[(ty*4+i) * 132 + 64 + tx*4] = make_float4(a[i][4], a[i][5], a[i][6], a[i][7]);
        }
        __syncthreads();             // Sc ready; all GEMM reads of Bs done

        // Prefetch next K tile into Bs — overlaps the scan below.
        if (kt + 1 < SS / 128) {
            #pragma unroll
            for (int p = 0; p < 16; ++p) {
                int idx = p * 128 + tid;
                int d   = idx >> 5;
                int kf4 = idx & 31;
                cpa16(&Bs[d * 128 + kf4 * 4],
                      &Kt[(size_t)d * SS + (kt + 1) * 128 + kf4 * 4]);
            }
            cpa_commit();
        }

        // Scan this thread's 32 columns of its row, ascending k, with a
        // max-of-4 fast path (selection semantics identical).
        #pragma unroll
        for (int m = 0; m < 8; ++m) {
            float4 s = *(const float4*)&Sc[srow * 132 + m * 16 + scg * 4];
            float mx4 = fmaxf(fmaxf(s.x, s.y), fmaxf(s.z, s.w));
            if (mx4 > tv[TOPK - 1]) {
                int k0 = kt * 128 + m * 16 + scg * 4;
                float sv[4] = {s.x, s.y, s.z, s.w};
                #pragma unroll
                for (int e = 0; e < 4; ++e) {
                    if (sv[e] > tv[TOPK - 1]) {
                        float vs = sv[e]; int is = k0 + e;
                        #pragma unroll
                        for (int t = 0; t < TOPK; ++t) {
                            if (vs > tv[t]) {
                                float tmpv = tv[t]; tv[t] = vs; vs = tmpv;
                                int tmpi = ti[t]; ti[t] = is; is = tmpi;
                            }
                        }
                    }
                }
            }
        }
        cpa_wait0();
        __syncthreads();             // next Bs tile resident; scans done
    }

    // Candidate lists into overlay (Bs/As dead now).
    #pragma unroll
    for (int t = 0; t < TOPK; ++t) {
        cv[tid * TOPK + t] = tv[t];
        ci[tid * TOPK + t] = ti[t];
    }
    __syncthreads();

    // Merge 4 candidate lists per row; ties -> lower index (lax.top_k).
    if (tid < 32) {
        int base = tid * 4 * TOPK;
        for (int s = 0; s < TOPK; ++s) {
            float best = neg_inf(); int bi = 0x7FFFFFFF; int bp = 0;
            for (int p = 0; p < 4 * TOPK; ++p) {
                float v = cv[base + p]; int ii = ci[base + p];
                if (v > best || (v == best && ii < bi)) { best = v; bi = ii; bp = p; }
            }
            cv[base + bp] = neg_inf();
            pb[tid * TOPK + s] = best;
            tix[tid * TOPK + s] = bi;
        }
        float mx = pb[tid * TOPK];
        float pr[TOPK]; float Z = 0.f;
        #pragma unroll
        for (int s = 0; s < TOPK; ++s) {
            float e = expf(pb[tid * TOPK + s] - mx);
            pr[s] = e; Z += e;
        }
        #pragma unroll
        for (int s = 0; s < TOPK; ++s) pb[tid * TOPK + s] = pr[s] / Z;
    }
    __syncthreads();

    const int q = qt * 32 + srow;
    const size_t abase = ((size_t)bh * SS + q) * SS;
    for (int t = scg; t < TOPK; t += 4)
        out_attn[abase + tix[srow * TOPK + t]] = pb[srow * TOPK + t];

    // Context: 4 threads per row, 16 dh-columns each.
    float acc[16];
    #pragma unroll
    for (int j = 0; j < 16; ++j) acc[j] = 0.f;
    #pragma unroll
    for (int t = 0; t < TOPK; ++t) {
        float p = pb[srow * TOPK + t];
        const float* vr = &Vb[(size_t)tix[srow * TOPK + t] * DH + scg * 16];
        #pragma unroll
        for (int j4 = 0; j4 < 4; ++j4) {
            float4 v = *(const float4*)&vr[j4 * 4];
            acc[j4*4+0] = fmaf(p, v.x, acc[j4*4+0]);
            acc[j4*4+1] = fmaf(p, v.y, acc[j4*4+1]);
            acc[j4*4+2] = fmaf(p, v.z, acc[j4*4+2]);
            acc[j4*4+3] = fmaf(p, v.w, acc[j4*4+3]);
        }
    }
    const int b_ = bh >> 3, h_ = bh & 7;
    float* dst = out_ctx + ((size_t)(b_ * SS + q)) * DD + h_ * DH + scg * 16;
    #pragma unroll
    for (int j4 = 0; j4 < 4; ++j4) {
        float4 o;
        o.x = acc[j4*4+0]; o.y = acc[j4*4+1];
        o.z = acc[j4*4+2]; o.w = acc[j4*4+3];
        *(float4*)&dst[j4 * 4] = o;
    }
}

// ---------------------------------------------------------------------------
extern "C" void kernel_launch(void* const* d_in, const int* in_sizes, int n_in,
                              void* d_out, int out_size)
{
    const float* x  = (const float*)d_in[0];
    const float* Wq = (const float*)d_in[1];
    const float* bq = (const float*)d_in[2];
    const float* Wk = (const float*)d_in[3];
    const float* bk = (const float*)d_in[4];
    const float* Wv = (const float*)d_in[5];
    const float* bv = (const float*)d_in[6];

    float* out_ctx  = (float*)d_out;
    float* out_attn = out_ctx + (size_t)BB * SS * DD;

    const int attn_smem = 14720 * 4;   // As + Bs + Sc floats
    cudaFuncSetAttribute(attn_kernel,
                         cudaFuncAttributeMaxDynamicSharedMemorySize, attn_smem);

    // attn output is exactly 10 nonzeros/row: zero-fill then scatter.
    cudaMemsetAsync(out_attn, 0, (size_t)BB * HH * SS * SS * sizeof(float));

    dim3 g1(DD / 64, (BB * SS) / 64, 3);   // (8, 128, 3)
    qkv_kernel<<<g1, 256>>>(x, Wq, bq, Wk, bk, Wv, bv);

    dim3 g2(SS / 32, BB * HH);             // (64, 32)
    attn_kernel<<<g2, 128, attn_smem>>>(out_ctx, out_attn);
}

// round 10
// speedup vs baseline: 1.0880x; 1.0880x over previous
#include <cuda_runtime.h>
#include <cstdint>

#define BB 4
#define HH 8
#define SS 2048
#define DD 512
#define DH 64
#define TOPK 10

// Scratch: Q,K transposed [bh][d][s] (d-major for attn GEMM staging);
// V row-major [bh][s][d] (context reads rows).
__device__ float g_Qt[BB*HH*DH*SS];
__device__ float g_Kt[BB*HH*DH*SS];
__device__ float g_V [BB*HH*SS*DH];

__device__ __forceinline__ float neg_inf() { return __int_as_float(0xff800000); }

__device__ __forceinline__ void cpa16(void* s, const void* g) {
    uint32_t sa = (uint32_t)__cvta_generic_to_shared(s);
    asm volatile("cp.async.cg.shared.global [%0], [%1], 16;" :: "r"(sa), "l"(g));
}
__device__ __forceinline__ void cpa_commit() {
    asm volatile("cp.async.commit_group;");
}
__device__ __forceinline__ void cpa_wait0() {
    asm volatile("cp.async.wait_group 0;");
}

// ---------------------------------------------------------------------------
// Kernel 1: Y = x @ W^T + b; Q,K scattered transposed, V row-major.
// Serial ascending-k FMA chain per output (bit-exact, matches reference).
// AT the 3-reg FFMA roofline. Also zero-fills out_attn (2 STG.128 per thread
// per k-tile, hidden in the FMA shadow; DRAM is otherwise idle here).
// ---------------------------------------------------------------------------
__global__ __launch_bounds__(256) void qkv_kernel(
    const float* __restrict__ x,
    const float* __restrict__ Wq, const float* __restrict__ bq,
    const float* __restrict__ Wk, const float* __restrict__ bk,
    const float* __restrict__ Wv, const float* __restrict__ bv,
    float* __restrict__ out_attn)
{
    const int which = blockIdx.z;
    const float* __restrict__ W    = (which == 0) ? Wq : (which == 1) ? Wk : Wv;
    const float* __restrict__ bias = (which == 0) ? bq : (which == 1) ? bk : bv;

    __shared__ float As[16][68];   // [k][m], padded
    __shared__ float Bs[16][68];   // [k][n], padded

    const int tid = threadIdx.x;
    const int tx  = tid & 15;       // 0..15 -> n
    const int ty  = tid >> 4;       // 0..15 -> m
    const int m0  = blockIdx.y * 64;
    const int n0  = blockIdx.x * 64;   // one head per n-tile (DH==64)

    const int lrow = tid >> 2;      // 0..63
    const int lk4  = tid & 3;       // 0..3

    // Zero-fill assignment: grid-stride over float4s of out_attn.
    const int  bid   = blockIdx.x + (blockIdx.y << 3) + (blockIdx.z << 10); // 0..3071
    const uint32_t gtid = tid + (bid << 8);            // 0..786431
    const uint32_t zstride = 3072u * 256u;             // total threads
    const uint32_t ztotal  = (uint32_t)((size_t)BB * HH * SS * SS / 4);  // 33554432
    float4* __restrict__ zdst = (float4*)out_attn;
    const float4 zf4 = make_float4(0.f, 0.f, 0.f, 0.f);

    float c[4][4];
    #pragma unroll
    for (int i = 0; i < 4; ++i)
        #pragma unroll
        for (int j = 0; j < 4; ++j) c[i][j] = 0.f;

    for (int kt = 0; kt < DD / 16; ++kt) {
        float4 av = *(const float4*)&x[(size_t)(m0 + lrow) * DD + kt * 16 + lk4 * 4];
        float4 bv4 = *(const float4*)&W[(size_t)(n0 + lrow) * DD + kt * 16 + lk4 * 4];
        __syncthreads();
        As[lk4 * 4 + 0][lrow] = av.x;
        As[lk4 * 4 + 1][lrow] = av.y;
        As[lk4 * 4 + 2][lrow] = av.z;
        As[lk4 * 4 + 3][lrow] = av.w;
        Bs[lk4 * 4 + 0][lrow] = bv4.x;
        Bs[lk4 * 4 + 1][lrow] = bv4.y;
        Bs[lk4 * 4 + 2][lrow] = bv4.z;
        Bs[lk4 * 4 + 3][lrow] = bv4.w;
        __syncthreads();

        // Two zero stores per tile, drained by the write buffer under the FMAs.
        {
            uint32_t i0 = gtid + (uint32_t)(kt * 2 + 0) * zstride;
            uint32_t i1 = gtid + (uint32_t)(kt * 2 + 1) * zstride;
            if (i0 < ztotal) zdst[i0] = zf4;
            if (i1 < ztotal) zdst[i1] = zf4;
        }

        // k ascending; each c[i][j] is one serial FMA chain over all 512 k.
        #pragma unroll
        for (int k = 0; k < 16; ++k) {
            float4 a  = *(const float4*)&As[k][ty * 4];
            float4 b4 = *(const float4*)&Bs[k][tx * 4];
            c[0][0] = fmaf(a.x, b4.x, c[0][0]); c[0][1] = fmaf(a.x, b4.y, c[0][1]);
            c[0][2] = fmaf(a.x, b4.z, c[0][2]); c[0][3] = fmaf(a.x, b4.w, c[0][3]);
            c[1][0] = fmaf(a.y, b4.x, c[1][0]); c[1][1] = fmaf(a.y, b4.y, c[1][1]);
            c[1][2] = fmaf(a.y, b4.z, c[1][2]); c[1][3] = fmaf(a.y, b4.w, c[1][3]);
            c[2][0] = fmaf(a.z, b4.x, c[2][0]); c[2][1] = fmaf(a.z, b4.y, c[2][1]);
            c[2][2] = fmaf(a.z, b4.z, c[2][2]); c[2][3] = fmaf(a.z, b4.w, c[2][3]);
            c[3][0] = fmaf(a.w, b4.x, c[3][0]); c[3][1] = fmaf(a.w, b4.y, c[3][1]);
            c[3][2] = fmaf(a.w, b4.z, c[3][2]); c[3][3] = fmaf(a.w, b4.w, c[3][3]);
        }
    }

    float4 biasv = *(const float4*)&bias[n0 + tx * 4];
    const int head = blockIdx.x;
    #pragma unroll
    for (int i = 0; i < 4; ++i) {
        int m  = m0 + ty * 4 + i;
        int b_ = m >> 11;        // m / 2048
        int s_ = m & 2047;
        float o0 = c[i][0] + biasv.x;
        float o1 = c[i][1] + biasv.y;
        float o2 = c[i][2] + biasv.z;
        float o3 = c[i][3] + biasv.w;
        if (which == 2) {
            float4 o; o.x = o0; o.y = o1; o.z = o2; o.w = o3;
            *(float4*)&g_V[(size_t)(((b_ * HH + head) * SS) + s_) * DH + tx * 4] = o;
        } else {
            float* dst = (which == 0) ? g_Qt : g_Kt;
            size_t base = ((size_t)(b_ * HH + head) * DH + tx * 4) * SS + s_;
            dst[base + 0 * SS] = o0;
            dst[base + 1 * SS] = o1;
            dst[base + 2 * SS] = o2;
            dst[base + 3 * SS] = o3;
        }
    }
}

// ---------------------------------------------------------------------------
// Kernel 2: per (b,h, 64-q-row tile). 256 threads; each a 4q x 4k sub-tile of
// a 64q x 64k score tile (same per-thread shape as the best kernel; ~96 regs).
// Double-buffered Bs: cp.async prefetch for tile t+1 issued BEFORE GEMM t,
// so the wait at the tile end is fully covered. d-loop strictly serial
// ascending per accumulator (bit-exact chain). Sc stride 68 (conflict-free).
// Scan keeps per-thread top-10; merge 4 lists/row; softmax; scatter attn
// (rest zeroed by qkv_kernel); context from V rows.
// ---------------------------------------------------------------------------
__global__ __launch_bounds__(256, 2) void attn_kernel(
    float* __restrict__ out_ctx, float* __restrict__ out_attn)
{
    extern __shared__ float sm[];
    float* As  = sm;                  // 64 x 68 [d][q]      (4352 floats)
    float* Bs0 = sm + 4352;           // 64 x 68 [d][k] buf0 (4352 floats)
    float* Bs1 = sm + 8704;           // 64 x 68 [d][k] buf1 (4352 floats)
    float* Sc  = sm + 13056;          // 64 x 68 [q][k]      (4352 floats)
    // Post-loop overlays (dead regions after the k-loop):
    float* cv  = Bs0;                 // 256*10 floats
    int*   ci  = (int*)(Bs0 + 2560);  // 256*10 ints (fits: 4352*2 >= 5120? 8704 total ok)
    float* pb  = As;                  // 64*10 floats
    int*   tix = (int*)(As + 640);    // 64*10 ints

    const int qt  = blockIdx.x;       // 0..31 (64 q-rows each)
    const int bh  = blockIdx.y;       // 0..31
    const int tid = threadIdx.x;      // 0..255
    const int ty  = tid >> 4;         // 0..15 -> q rows ty*4..+3
    const int tx  = tid & 15;         // 0..15 -> k cols tx*4..+3
    const int srow = tid >> 2;        // 0..63 scan row
    const int scg  = tid & 3;         // 0..3  scan col group

    const float* __restrict__ Qt = g_Qt + (size_t)bh * DH * SS;
    const float* __restrict__ Kt = g_Kt + (size_t)bh * DH * SS;
    const float* __restrict__ Vb = g_V  + (size_t)bh * SS * DH;

    // Stage As = Q^T tile (64d x 64q), scaled by 1/8 (exact pow2).
    #pragma unroll
    for (int p = 0; p < 4; ++p) {
        int idx = p * 256 + tid;      // 0..1023 float4s
        int d   = idx >> 4;
        int qf4 = idx & 15;
        float4 v = *(const float4*)&Qt[(size_t)d * SS + qt * 64 + qf4 * 4];
        v.x *= 0.125f; v.y *= 0.125f; v.z *= 0.125f; v.w *= 0.125f;
        *(float4*)&As[d * 68 + qf4 * 4] = v;
    }

    // Preload K tile 0 into Bs0.
    #pragma unroll
    for (int p = 0; p < 4; ++p) {
        int idx = p * 256 + tid;      // 0..1023 float4s
        int d   = idx >> 4;
        int kf4 = idx & 15;
        cpa16(&Bs0[d * 68 + kf4 * 4], &Kt[(size_t)d * SS + kf4 * 4]);
    }
    cpa_commit();
    cpa_wait0();
    __syncthreads();                   // As + Bs0 ready

    float tv[TOPK];
    int   ti[TOPK];
    #pragma unroll
    for (int t = 0; t < TOPK; ++t) { tv[t] = neg_inf(); ti[t] = 0x7FFFFFFF; }

    const int NT = SS / 64;            // 32 tiles
    for (int kt = 0; kt < NT; ++kt) {
        float* Bc = (kt & 1) ? Bs1 : Bs0;
        float* Bn = (kt & 1) ? Bs0 : Bs1;

        // Prefetch tile kt+1 into the other buffer; covered by GEMM + scan.
        if (kt + 1 < NT) {
            #pragma unroll
            for (int p = 0; p < 4; ++p) {
                int idx = p * 256 + tid;
                int d   = idx >> 4;
                int kf4 = idx & 15;
                cpa16(&Bn[d * 68 + kf4 * 4],
                      &Kt[(size_t)d * SS + (kt + 1) * 64 + kf4 * 4]);
            }
            cpa_commit();
        }

        // GEMM: 4x4 accumulators, d ascending serial per accumulator.
        float a0[4], a1[4], a2[4], a3[4];
        #pragma unroll
        for (int j = 0; j < 4; ++j) { a0[j]=0.f; a1[j]=0.f; a2[j]=0.f; a3[j]=0.f; }
        #pragma unroll 8
        for (int d = 0; d < 64; ++d) {
            float4 q = *(const float4*)&As[d * 68 + ty * 4];
            float4 k = *(const float4*)&Bc[d * 68 + tx * 4];
            a0[0]=fmaf(q.x,k.x,a0[0]); a0[1]=fmaf(q.x,k.y,a0[1]);
            a0[2]=fmaf(q.x,k.z,a0[2]); a0[3]=fmaf(q.x,k.w,a0[3]);
            a1[0]=fmaf(q.y,k.x,a1[0]); a1[1]=fmaf(q.y,k.y,a1[1]);
            a1[2]=fmaf(q.y,k.z,a1[2]); a1[3]=fmaf(q.y,k.w,a1[3]);
            a2[0]=fmaf(q.z,k.x,a2[0]); a2[1]=fmaf(q.z,k.y,a2[1]);
            a2[2]=fmaf(q.z,k.z,a2[2]); a2[3]=fmaf(q.z,k.w,a2[3]);
            a3[0]=fmaf(q.w,k.x,a3[0]); a3[1]=fmaf(q.w,k.y,a3[1]);
            a3[2]=fmaf(q.w,k.z,a3[2]); a3[3]=fmaf(q.w,k.w,a3[3]);
        }
        // Dump scores to smem (stride 68: 4-wavefront optimal).
        *(float4*)&Sc[(ty*4+0)*68 + tx*4] = make_float4(a0[0],a0[1],a0[2],a0[3]);
        *(float4*)&Sc[(ty*4+1)*68 + tx*4] = make_float4(a1[0],a1[1],a1[2],a1[3]);
        *(float4*)&Sc[(ty*4+2)*68 + tx*4] = make_float4(a2[0],a2[1],a2[2],a2[3]);
        *(float4*)&Sc[(ty*4+3)*68 + tx*4] = make_float4(a3[0],a3[1],a3[2],a3[3]);
        __syncthreads();              // Sc ready

        // Scan this thread's 16 columns of its row, ascending k, with a
        // max-of-4 fast path (selection semantics identical).
        #pragma unroll
        for (int j4 = 0; j4 < 4; ++j4) {
            float4 s = *(const float4*)&Sc[srow * 68 + scg * 16 + j4 * 4];
            float mx4 = fmaxf(fmaxf(s.x, s.y), fmaxf(s.z, s.w));
            if (mx4 > tv[TOPK - 1]) {
                int k0 = kt * 64 + scg * 16 + j4 * 4;
                float sv[4] = {s.x, s.y, s.z, s.w};
                #pragma unroll
                for (int e = 0; e < 4; ++e) {
                    if (sv[e] > tv[TOPK - 1]) {
                        float vs = sv[e]; int is = k0 + e;
                        #pragma unroll
                        for (int t = 0; t < TOPK; ++t) {
                            if (vs > tv[t]) {
                                float tmpv = tv[t]; tv[t] = vs; vs = tmpv;
                                int tmpi = ti[t]; ti[t] = is; is = tmpi;
                            }
                        }
                    }
                }
            }
        }
        cpa_wait0();                  // next tile resident (fully covered)
        __syncthreads();              // scans done; safe to reuse buffers
    }

    // Candidate lists into overlay (Bs0/Bs1/As dead now).
    #pragma unroll
    for (int t = 0; t < TOPK; ++t) {
        cv[tid * TOPK + t] = tv[t];
        ci[tid * TOPK + t] = ti[t];
    }
    __syncthreads();

    // Merge 4 candidate lists per row; ties -> lower index (lax.top_k).
    if (tid < 64) {
        int base = tid * 4 * TOPK;
        for (int s = 0; s < TOPK; ++s) {
            float best = neg_inf(); int bi = 0x7FFFFFFF; int bp = 0;
            for (int p = 0; p < 4 * TOPK; ++p) {
                float v = cv[base + p]; int ii = ci[base + p];
                if (v > best || (v == best && ii < bi)) { best = v; bi = ii; bp = p; }
            }
            cv[base + bp] = neg_inf();
            pb[tid * TOPK + s] = best;
            tix[tid * TOPK + s] = bi;
        }
        float mx = pb[tid * TOPK];
        float pr[TOPK]; float Z = 0.f;
        #pragma unroll
        for (int s = 0; s < TOPK; ++s) {
            float e = expf(pb[tid * TOPK + s] - mx);
            pr[s] = e; Z += e;
        }
        #pragma unroll
        for (int s = 0; s < TOPK; ++s) pb[tid * TOPK + s] = pr[s] / Z;
    }
    __syncthreads();

    const int q = qt * 64 + srow;
    const size_t abase = ((size_t)bh * SS + q) * SS;
    for (int t = scg; t < TOPK; t += 4)
        out_attn[abase + tix[srow * TOPK + t]] = pb[srow * TOPK + t];

    // Context: 4 threads per row, 16 dh-columns each.
    float acc[16];
    #pragma unroll
    for (int j = 0; j < 16; ++j) acc[j] = 0.f;
    #pragma unroll
    for (int t = 0; t < TOPK; ++t) {
        float p = pb[srow * TOPK + t];
        const float* vr = &Vb[(size_t)tix[srow * TOPK + t] * DH + scg * 16];
        #pragma unroll
        for (int j4 = 0; j4 < 4; ++j4) {
            float4 v = *(const float4*)&vr[j4 * 4];
            acc[j4*4+0] = fmaf(p, v.x, acc[j4*4+0]);
            acc[j4*4+1] = fmaf(p, v.y, acc[j4*4+1]);
            acc[j4*4+2] = fmaf(p, v.z, acc[j4*4+2]);
            acc[j4*4+3] = fmaf(p, v.w, acc[j4*4+3]);
        }
    }
    const int b_ = bh >> 3, h_ = bh & 7;
    float* dst = out_ctx + ((size_t)(b_ * SS + q)) * DD + h_ * DH + scg * 16;
    #pragma unroll
    for (int j4 = 0; j4 < 4; ++j4) {
        float4 o;
        o.x = acc[j4*4+0]; o.y = acc[j4*4+1];
        o.z = acc[j4*4+2]; o.w = acc[j4*4+3];
        *(float4*)&dst[j4 * 4] = o;
    }
}

// ---------------------------------------------------------------------------
extern "C" void kernel_launch(void* const* d_in, const int* in_sizes, int n_in,
                              void* d_out, int out_size)
{
    const float* x  = (const float*)d_in[0];
    const float* Wq = (const float*)d_in[1];
    const float* bq = (const float*)d_in[2];
    const float* Wk = (const float*)d_in[3];
    const float* bk = (const float*)d_in[4];
    const float* Wv = (const float*)d_in[5];
    const float* bv = (const float*)d_in[6];

    float* out_ctx  = (float*)d_out;
    float* out_attn = out_ctx + (size_t)BB * SS * DD;

    const int attn_smem = 17408 * 4;   // As + Bs0 + Bs1 + Sc floats = 69632 B
    cudaFuncSetAttribute(attn_kernel,
                         cudaFuncAttributeMaxDynamicSharedMemorySize, attn_smem);

    // qkv also zero-fills out_attn (grid-stride, hidden in FMA shadow).
    dim3 g1(DD / 64, (BB * SS) / 64, 3);   // (8, 128, 3)
    qkv_kernel<<<g1, 256>>>(x, Wq, bq, Wk, bk, Wv, bv, out_attn);

    dim3 g2(SS / 64, BB * HH);             // (32, 32)
    attn_kernel<<<g2, 256, attn_smem>>>(out_ctx, out_attn);
}

// round 11
// speedup vs baseline: 1.1470x; 1.0543x over previous
#include <cuda_runtime.h>
#include <cstdint>

#define BB 4
#define HH 8
#define SS 2048
#define DD 512
#define DH 64
#define TOPK 10

// Scratch: Q,K transposed [bh][d][s] (d-major for attn GEMM staging);
// V row-major [bh][s][d] (context reads rows).
__device__ float g_Qt[BB*HH*DH*SS];
__device__ float g_Kt[BB*HH*DH*SS];
__device__ float g_V [BB*HH*SS*DH];

__device__ __forceinline__ float neg_inf() { return __int_as_float(0xff800000); }

__device__ __forceinline__ void cpa16(void* s, const void* g) {
    uint32_t sa = (uint32_t)__cvta_generic_to_shared(s);
    asm volatile("cp.async.cg.shared.global [%0], [%1], 16;" :: "r"(sa), "l"(g));
}
__device__ __forceinline__ void cpa_commit() {
    asm volatile("cp.async.commit_group;");
}
__device__ __forceinline__ void cpa_wait0() {
    asm volatile("cp.async.wait_group 0;");
}

// ---------------------------------------------------------------------------
// Kernel 1 (R10 form): Y = x @ W^T + b; Q,K scattered transposed, V row-major.
// Serial ascending-k FMA chain per output (bit-exact, matches reference).
// AT the 3-reg FFMA roofline. Also zero-fills out_attn (2 STG.128 per thread
// per k-tile, hidden in the FMA shadow; DRAM is otherwise idle here).
// ---------------------------------------------------------------------------
__global__ __launch_bounds__(256) void qkv_kernel(
    const float* __restrict__ x,
    const float* __restrict__ Wq, const float* __restrict__ bq,
    const float* __restrict__ Wk, const float* __restrict__ bk,
    const float* __restrict__ Wv, const float* __restrict__ bv,
    float* __restrict__ out_attn)
{
    const int which = blockIdx.z;
    const float* __restrict__ W    = (which == 0) ? Wq : (which == 1) ? Wk : Wv;
    const float* __restrict__ bias = (which == 0) ? bq : (which == 1) ? bk : bv;

    __shared__ float As[16][68];   // [k][m], padded
    __shared__ float Bs[16][68];   // [k][n], padded

    const int tid = threadIdx.x;
    const int tx  = tid & 15;       // 0..15 -> n
    const int ty  = tid >> 4;       // 0..15 -> m
    const int m0  = blockIdx.y * 64;
    const int n0  = blockIdx.x * 64;   // one head per n-tile (DH==64)

    const int lrow = tid >> 2;      // 0..63
    const int lk4  = tid & 3;       // 0..3

    // Zero-fill assignment: grid-stride over float4s of out_attn.
    const int  bid   = blockIdx.x + (blockIdx.y << 3) + (blockIdx.z << 10); // 0..3071
    const uint32_t gtid = tid + (bid << 8);            // 0..786431
    const uint32_t zstride = 3072u * 256u;             // total threads
    const uint32_t ztotal  = (uint32_t)((size_t)BB * HH * SS * SS / 4);  // 33554432
    float4* __restrict__ zdst = (float4*)out_attn;
    const float4 zf4 = make_float4(0.f, 0.f, 0.f, 0.f);

    float c[4][4];
    #pragma unroll
    for (int i = 0; i < 4; ++i)
        #pragma unroll
        for (int j = 0; j < 4; ++j) c[i][j] = 0.f;

    for (int kt = 0; kt < DD / 16; ++kt) {
        float4 av = *(const float4*)&x[(size_t)(m0 + lrow) * DD + kt * 16 + lk4 * 4];
        float4 bv4 = *(const float4*)&W[(size_t)(n0 + lrow) * DD + kt * 16 + lk4 * 4];
        __syncthreads();
        As[lk4 * 4 + 0][lrow] = av.x;
        As[lk4 * 4 + 1][lrow] = av.y;
        As[lk4 * 4 + 2][lrow] = av.z;
        As[lk4 * 4 + 3][lrow] = av.w;
        Bs[lk4 * 4 + 0][lrow] = bv4.x;
        Bs[lk4 * 4 + 1][lrow] = bv4.y;
        Bs[lk4 * 4 + 2][lrow] = bv4.z;
        Bs[lk4 * 4 + 3][lrow] = bv4.w;
        __syncthreads();

        // Two zero stores per tile, drained by the write buffer under the FMAs.
        {
            uint32_t i0 = gtid + (uint32_t)(kt * 2 + 0) * zstride;
            uint32_t i1 = gtid + (uint32_t)(kt * 2 + 1) * zstride;
            if (i0 < ztotal) zdst[i0] = zf4;
            if (i1 < ztotal) zdst[i1] = zf4;
        }

        // k ascending; each c[i][j] is one serial FMA chain over all 512 k.
        #pragma unroll
        for (int k = 0; k < 16; ++k) {
            float4 a  = *(const float4*)&As[k][ty * 4];
            float4 b4 = *(const float4*)&Bs[k][tx * 4];
            c[0][0] = fmaf(a.x, b4.x, c[0][0]); c[0][1] = fmaf(a.x, b4.y, c[0][1]);
            c[0][2] = fmaf(a.x, b4.z, c[0][2]); c[0][3] = fmaf(a.x, b4.w, c[0][3]);
            c[1][0] = fmaf(a.y, b4.x, c[1][0]); c[1][1] = fmaf(a.y, b4.y, c[1][1]);
            c[1][2] = fmaf(a.y, b4.z, c[1][2]); c[1][3] = fmaf(a.y, b4.w, c[1][3]);
            c[2][0] = fmaf(a.z, b4.x, c[2][0]); c[2][1] = fmaf(a.z, b4.y, c[2][1]);
            c[2][2] = fmaf(a.z, b4.z, c[2][2]); c[2][3] = fmaf(a.z, b4.w, c[2][3]);
            c[3][0] = fmaf(a.w, b4.x, c[3][0]); c[3][1] = fmaf(a.w, b4.y, c[3][1]);
            c[3][2] = fmaf(a.w, b4.z, c[3][2]); c[3][3] = fmaf(a.w, b4.w, c[3][3]);
        }
    }

    float4 biasv = *(const float4*)&bias[n0 + tx * 4];
    const int head = blockIdx.x;
    #pragma unroll
    for (int i = 0; i < 4; ++i) {
        int m  = m0 + ty * 4 + i;
        int b_ = m >> 11;        // m / 2048
        int s_ = m & 2047;
        float o0 = c[i][0] + biasv.x;
        float o1 = c[i][1] + biasv.y;
        float o2 = c[i][2] + biasv.z;
        float o3 = c[i][3] + biasv.w;
        if (which == 2) {
            float4 o; o.x = o0; o.y = o1; o.z = o2; o.w = o3;
            *(float4*)&g_V[(size_t)(((b_ * HH + head) * SS) + s_) * DH + tx * 4] = o;
        } else {
            float* dst = (which == 0) ? g_Qt : g_Kt;
            size_t base = ((size_t)(b_ * HH + head) * DH + tx * 4) * SS + s_;
            dst[base + 0 * SS] = o0;
            dst[base + 1 * SS] = o1;
            dst[base + 2 * SS] = o2;
            dst[base + 3 * SS] = o3;
        }
    }
}

// ---------------------------------------------------------------------------
// Kernel 2 (R8 form — best measured attn). Per (b,h, 32-q-row tile): 128
// threads, each a 4q x 4k sub-tile of a 32q x 64k score tile; d-loop strictly
// serial ascending per accumulator (bit-exact chain). Single Bs with cp.async
// prefetch overlapping the scan. Sc stride 68 (conflict-free). Scan keeps
// per-thread top-10; merge 4 lists/row; softmax; scatter attn (rest zeroed
// by qkv_kernel); context from V rows.
// ---------------------------------------------------------------------------
__global__ __launch_bounds__(128, 5) void attn_kernel(
    float* __restrict__ out_ctx, float* __restrict__ out_attn)
{
    __shared__ float As[64 * 36];        // Q  [d][q]
    __shared__ float Bs[64 * 68];        // K  [d][k]
    __shared__ float Sc[32 * 68];        // scores [q][k]
    // Post-loop overlays (regions dead after the last GEMM/scan):
    float* cv  = Bs;                     // 128*10 floats
    int*   ci  = (int*)(Bs + 1280);      // 128*10 ints
    float* pb  = As;                     // 32*10 floats
    int*   tix = (int*)(As + 320);       // 32*10 ints

    const int qt  = blockIdx.x;      // 0..63 (32 q-rows each)
    const int bh  = blockIdx.y;      // 0..31
    const int tid = threadIdx.x;     // 0..127
    const int ty  = tid >> 4;        // 0..7  -> q rows ty*4..+3
    const int tx  = tid & 15;        // 0..15 -> k cols tx*4..+3
    const int srow = tid >> 2;       // 0..31 scan row
    const int scg  = tid & 3;        // 0..3  scan col group

    const float* __restrict__ Qt = g_Qt + (size_t)bh * DH * SS;
    const float* __restrict__ Kt = g_Kt + (size_t)bh * DH * SS;
    const float* __restrict__ Vb = g_V  + (size_t)bh * SS * DH;

    // Stage As = Q^T tile (64d x 32q), scaled by 1/8 (exact pow2).
    #pragma unroll
    for (int p = 0; p < 4; ++p) {
        int idx = p * 128 + tid;     // 0..511 float4s
        int d   = idx >> 3;
        int qf4 = idx & 7;
        float4 v = *(const float4*)&Qt[(size_t)d * SS + qt * 32 + qf4 * 4];
        v.x *= 0.125f; v.y *= 0.125f; v.z *= 0.125f; v.w *= 0.125f;
        *(float4*)&As[d * 36 + qf4 * 4] = v;
    }

    // Preload K tile 0 via cp.async (8 float4 per thread).
    #pragma unroll
    for (int p = 0; p < 8; ++p) {
        int idx = p * 128 + tid;     // 0..1023 float4s
        int d   = idx >> 4;
        int kf4 = idx & 15;
        cpa16(&Bs[d * 68 + kf4 * 4], &Kt[(size_t)d * SS + kf4 * 4]);
    }
    cpa_commit();
    cpa_wait0();
    __syncthreads();                  // As + Bs(tile 0) ready

    float tv[TOPK];
    int   ti[TOPK];
    #pragma unroll
    for (int t = 0; t < TOPK; ++t) { tv[t] = neg_inf(); ti[t] = 0x7FFFFFFF; }

    for (int kt = 0; kt < SS / 64; ++kt) {
        // GEMM: 4x4 accumulators, d ascending serial per accumulator.
        float a0[4], a1[4], a2[4], a3[4];
        #pragma unroll
        for (int j = 0; j < 4; ++j) { a0[j]=0.f; a1[j]=0.f; a2[j]=0.f; a3[j]=0.f; }
        #pragma unroll 8
        for (int d = 0; d < 64; ++d) {
            float4 q = *(const float4*)&As[d * 36 + ty * 4];
            float4 k = *(const float4*)&Bs[d * 68 + tx * 4];
            a0[0]=fmaf(q.x,k.x,a0[0]); a0[1]=fmaf(q.x,k.y,a0[1]);
            a0[2]=fmaf(q.x,k.z,a0[2]); a0[3]=fmaf(q.x,k.w,a0[3]);
            a1[0]=fmaf(q.y,k.x,a1[0]); a1[1]=fmaf(q.y,k.y,a1[1]);
            a1[2]=fmaf(q.y,k.z,a1[2]); a1[3]=fmaf(q.y,k.w,a1[3]);
            a2[0]=fmaf(q.z,k.x,a2[0]); a2[1]=fmaf(q.z,k.y,a2[1]);
            a2[2]=fmaf(q.z,k.z,a2[2]); a2[3]=fmaf(q.z,k.w,a2[3]);
            a3[0]=fmaf(q.w,k.x,a3[0]); a3[1]=fmaf(q.w,k.y,a3[1]);
            a3[2]=fmaf(q.w,k.z,a3[2]); a3[3]=fmaf(q.w,k.w,a3[3]);
        }
        // Dump scores to smem.
        *(float4*)&Sc[(ty*4+0)*68 + tx*4] = make_float4(a0[0],a0[1],a0[2],a0[3]);
        *(float4*)&Sc[(ty*4+1)*68 + tx*4] = make_float4(a1[0],a1[1],a1[2],a1[3]);
        *(float4*)&Sc[(ty*4+2)*68 + tx*4] = make_float4(a2[0],a2[1],a2[2],a2[3]);
        *(float4*)&Sc[(ty*4+3)*68 + tx*4] = make_float4(a3[0],a3[1],a3[2],a3[3]);
        __syncthreads();             // all GEMM reads of Bs done; Sc ready

        // Prefetch next K tile into Bs — overlaps the scan below.
        if (kt + 1 < SS / 64) {
            #pragma unroll
            for (int p = 0; p < 8; ++p) {
                int idx = p * 128 + tid;
                int d   = idx >> 4;
                int kf4 = idx & 15;
                cpa16(&Bs[d * 68 + kf4 * 4],
                      &Kt[(size_t)d * SS + (kt + 1) * 64 + kf4 * 4]);
            }
            cpa_commit();
        }

        // Scan this thread's 16 columns of its row, ascending k, with a
        // max-of-4 fast path (selection semantics identical).
        #pragma unroll
        for (int j4 = 0; j4 < 4; ++j4) {
            float4 s = *(const float4*)&Sc[srow * 68 + scg * 16 + j4 * 4];
            float mx4 = fmaxf(fmaxf(s.x, s.y), fmaxf(s.z, s.w));
            if (mx4 > tv[TOPK - 1]) {
                int k0 = kt * 64 + scg * 16 + j4 * 4;
                float sv[4] = {s.x, s.y, s.z, s.w};
                #pragma unroll
                for (int e = 0; e < 4; ++e) {
                    if (sv[e] > tv[TOPK - 1]) {
                        float vs = sv[e]; int is = k0 + e;
                        #pragma unroll
                        for (int t = 0; t < TOPK; ++t) {
                            if (vs > tv[t]) {
                                float tmpv = tv[t]; tv[t] = vs; vs = tmpv;
                                int tmpi = ti[t]; ti[t] = is; is = tmpi;
                            }
                        }
                    }
                }
            }
        }
        cpa_wait0();
        __syncthreads();             // next Bs tile resident; scans done
    }

    // Candidate lists into overlay (Bs dead after final sync above).
    #pragma unroll
    for (int t = 0; t < TOPK; ++t) {
        cv[tid * TOPK + t] = tv[t];
        ci[tid * TOPK + t] = ti[t];
    }
    __syncthreads();

    // Merge 4 candidate lists per row; ties -> lower index (lax.top_k).
    if (tid < 32) {
        int base = tid * 4 * TOPK;
        for (int s = 0; s < TOPK; ++s) {
            float best = neg_inf(); int bi = 0x7FFFFFFF; int bp = 0;
            for (int p = 0; p < 4 * TOPK; ++p) {
                float v = cv[base + p]; int ii = ci[base + p];
                if (v > best || (v == best && ii < bi)) { best = v; bi = ii; bp = p; }
            }
            cv[base + bp] = neg_inf();
            pb[tid * TOPK + s] = best;
            tix[tid * TOPK + s] = bi;
        }
        float mx = pb[tid * TOPK];
        float pr[TOPK]; float Z = 0.f;
        #pragma unroll
        for (int s = 0; s < TOPK; ++s) {
            float e = expf(pb[tid * TOPK + s] - mx);
            pr[s] = e; Z += e;
        }
        #pragma unroll
        for (int s = 0; s < TOPK; ++s) pb[tid * TOPK + s] = pr[s] / Z;
    }
    __syncthreads();

    const int q = qt * 32 + srow;
    const size_t abase = ((size_t)bh * SS + q) * SS;
    for (int t = scg; t < TOPK; t += 4)
        out_attn[abase + tix[srow * TOPK + t]] = pb[srow * TOPK + t];

    // Context: 4 threads per row, 16 dh-columns each.
    float acc[16];
    #pragma unroll
    for (int j = 0; j < 16; ++j) acc[j] = 0.f;
    #pragma unroll
    for (int t = 0; t < TOPK; ++t) {
        float p = pb[srow * TOPK + t];
        const float* vr = &Vb[(size_t)tix[srow * TOPK + t] * DH + scg * 16];
        #pragma unroll
        for (int j4 = 0; j4 < 4; ++j4) {
            float4 v = *(const float4*)&vr[j4 * 4];
            acc[j4*4+0] = fmaf(p, v.x, acc[j4*4+0]);
            acc[j4*4+1] = fmaf(p, v.y, acc[j4*4+1]);
            acc[j4*4+2] = fmaf(p, v.z, acc[j4*4+2]);
            acc[j4*4+3] = fmaf(p, v.w, acc[j4*4+3]);
        }
    }
    const int b_ = bh >> 3, h_ = bh & 7;
    float* dst = out_ctx + ((size_t)(b_ * SS + q)) * DD + h_ * DH + scg * 16;
    #pragma unroll
    for (int j4 = 0; j4 < 4; ++j4) {
        float4 o;
        o.x = acc[j4*4+0]; o.y = acc[j4*4+1];
        o.z = acc[j4*4+2]; o.w = acc[j4*4+3];
        *(float4*)&dst[j4 * 4] = o;
    }
}

// ---------------------------------------------------------------------------
extern "C" void kernel_launch(void* const* d_in, const int* in_sizes, int n_in,
                              void* d_out, int out_size)
{
    const float* x  = (const float*)d_in[0];
    const float* Wq = (const float*)d_in[1];
    const float* bq = (const float*)d_in[2];
    const float* Wk = (const float*)d_in[3];
    const float* bk = (const float*)d_in[4];
    const float* Wv = (const float*)d_in[5];
    const float* bv = (const float*)d_in[6];

    float* out_ctx  = (float*)d_out;
    float* out_attn = out_ctx + (size_t)BB * SS * DD;

    // qkv also zero-fills out_attn (grid-stride, hidden in FMA shadow).
    dim3 g1(DD / 64, (BB * SS) / 64, 3);   // (8, 128, 3)
    qkv_kernel<<<g1, 256>>>(x, Wq, bq, Wk, bk, Wv, bv, out_attn);

    dim3 g2(SS / 32, BB * HH);             // (64, 32)
    attn_kernel<<<g2, 128>>>(out_ctx, out_attn);
}